// round 12
// baseline (speedup 1.0000x reference)
#include <cuda_runtime.h>
#include <cuda_fp16.h>
#include <math.h>
#include <stdint.h>

// ============================================================================
// ConvolutionKAN as mma.sync fp16 GEMM (sm_100-safe, fp32 accumulate):
//   out[61504,128] = A[61504,2592] @ W[2592,128] + bias
//   K layout: k in [0,2304): spline (i=k>>3, c=k&7, uniform cubic B-spline
//             closed form); k in [2304,2592): silu(x_i).
// R12: WARP SPECIALIZATION. 384 threads: warps 0-7 pure MMA consumers,
//      warps 8-11 pure producers (A build + W cp.async + input prefetch).
//      Decorrelates the latency chains that serialized every prior round.
// ============================================================================

#define N_TOTAL   61504
#define K_TOTAL   2592
#define FILTERS   128
#define BM        64
#define NKT       81                   // 2592 / 32
#define NSPLINE   72                   // tiles 0..71: spline, 72..80: silu

#define ASTB       80                  // A row stride (bytes), conflict-free
#define A_STAGE_B  (BM * ASTB)         // 5120
#define W_STAGE_B  8192                // 32k * 128o * 2B (frag-ordered)
#define SMEM_W_OFF (2 * A_STAGE_B)     // 10240
#define SMEM_TOTAL (2 * A_STAGE_B + 3 * W_STAGE_B)   // 34816 B

// W in m16n8k16 B-fragment word order per 32-k tile (2048 words):
//   word = ks*1024 + ob*64 + lane*2 + r
//   halfs: k = kt*32 + ks*16 + 2*(lane&3) + 8*r + hh,  o = ob*8 + (lane>>2)
__device__ __half g_Wh[K_TOTAL * FILTERS];

// ---------------------------------------------------------------- helpers --
__device__ __forceinline__ uint32_t pack2(float a, float b) {
    __half2 h = __floats2half2_rn(a, b);
    return *reinterpret_cast<uint32_t*>(&h);
}
__device__ __forceinline__ void sts16(uint32_t addr, uint32_t a, uint32_t b,
                                      uint32_t c, uint32_t d) {
    asm volatile("st.shared.v4.b32 [%0], {%1,%2,%3,%4};"
                 :: "r"(addr), "r"(a), "r"(b), "r"(c), "r"(d) : "memory");
}
__device__ __forceinline__ void lds_v2(uint32_t addr, uint32_t& a, uint32_t& b) {
    asm volatile("ld.shared.v2.b32 {%0,%1}, [%2];" : "=r"(a), "=r"(b) : "r"(addr));
}
__device__ __forceinline__ void ldsm4(uint32_t addr, uint32_t* r) {
    asm volatile("ldmatrix.sync.aligned.m8n8.x4.shared.b16 {%0,%1,%2,%3}, [%4];"
                 : "=r"(r[0]), "=r"(r[1]), "=r"(r[2]), "=r"(r[3]) : "r"(addr));
}
__device__ __forceinline__ void mma16(float* d, const uint32_t* a,
                                      uint32_t b0, uint32_t b1) {
    asm volatile(
        "mma.sync.aligned.m16n8k16.row.col.f32.f16.f16.f32 "
        "{%0,%1,%2,%3}, {%4,%5,%6,%7}, {%8,%9}, {%0,%1,%2,%3};"
        : "+f"(d[0]), "+f"(d[1]), "+f"(d[2]), "+f"(d[3])
        : "r"(a[0]), "r"(a[1]), "r"(a[2]), "r"(a[3]), "r"(b0), "r"(b1));
}
__device__ __forceinline__ void cpasync16(uint32_t saddr, const void* gptr) {
    asm volatile("cp.async.cg.shared.global [%0], [%1], 16;"
                 :: "r"(saddr), "l"(__cvta_generic_to_global(gptr)) : "memory");
}
#define CP_COMMIT()  asm volatile("cp.async.commit_group;" ::: "memory")
#define CP_WAIT1()   asm volatile("cp.async.wait_group 1;" ::: "memory")

// --------------------------------------------------------- weight fuse -----
__global__ void fuse_weights(const float* __restrict__ sk,   // [288,8,128]
                             const float* __restrict__ sc) { // [288,128]
    int w = blockIdx.x * 256 + threadIdx.x;                  // uint32 words
    if (w >= K_TOTAL * FILTERS / 2) return;
    int kt   = w >> 11;                 // 2048 words per 32-k tile
    int rem  = w & 2047;
    int ks   = rem >> 10;
    int ob   = (rem >> 6) & 15;
    int l    = (rem >> 1) & 31;
    int r    = rem & 1;
    int o    = ob * 8 + (l >> 2);
    int kb   = kt * 32 + ks * 16 + 2 * (l & 3) + 8 * r;
    float v[2];
#pragma unroll
    for (int hh = 0; hh < 2; ++hh) {
        int k = kb + hh;
        if (k < 2304) {
            int i = k >> 3;
            v[hh] = sk[k * 128 + o] * sc[i * 128 + o];
        } else {
            v[hh] = sc[(k - 2304) * 128 + o];
        }
    }
    ((uint32_t*)g_Wh)[w] = pack2(v[0], v[1]);
}

// ------------------------------------------------------------ A builder ----
// Producer thread (row, qb in {0,2}) builds quarters qb,qb+1 of its row
// (32 B). Spline: channels i = kt*4 + qb, +1 (prefetched float2). Silu:
// channels 16*(qb/2) .. +15 of 32-block.
__device__ __forceinline__ float2 prefetch_x2(int kt, int qb,
                                              const float* __restrict__ rowbase) {
    int i  = kt * 4 + qb;
    int di = i / 96;
    int rm = i - di * 96;
    return *reinterpret_cast<const float2*>(
        rowbase + (di * 64 + (rm >> 5)) * 32 + (rm & 31));
}

__device__ __forceinline__ void spline8(float x, uint32_t dst) {
    float tp = (x + 1.0f) * 2.5f;                    // uniform grid, h = 0.4
    int j = (int)floorf(tp);
    j = max(0, min(4, j));
    float u  = tp - (float)j;
    float um = 1.0f - u;
    float u2 = u * u, u3 = u2 * u;
    float b0 = um * um * um * (1.0f / 6.0f);
    float b1 = (3.0f * u3 - 6.0f * u2 + 4.0f) * (1.0f / 6.0f);
    float b2 = (-3.0f * u3 + 3.0f * u2 + 3.0f * u + 1.0f) * (1.0f / 6.0f);
    float b3 = u3 * (1.0f / 6.0f);
    float f[8];
#pragma unroll
    for (int z = 0; z < 8; ++z) f[z] = 0.f;
    f[j]     = b0;
    f[j + 1] = b1;
    f[j + 2] = b2;
    f[j + 3] = b3;
    sts16(dst, pack2(f[0], f[1]), pack2(f[2], f[3]),
               pack2(f[4], f[5]), pack2(f[6], f[7]));
}

__device__ __forceinline__ void build_pair(int kt, int qb, float2 xv,
                                           uint32_t dst,
                                           const float* __restrict__ rowbase) {
    if (kt < NSPLINE) {
        spline8(xv.x, dst + qb * 16);
        spline8(xv.y, dst + qb * 16 + 16);
    } else {
        int ib = kt - NSPLINE;                       // 32-channel block
        int di = ib / 3;
        int dj = ib - di * 3;
        const float* src = rowbase + (di * 64 + dj) * 32 + qb * 8;
#pragma unroll
        for (int half = 0; half < 2; ++half) {
            float4 x0 = *reinterpret_cast<const float4*>(src + half * 8);
            float4 x1 = *reinterpret_cast<const float4*>(src + half * 8 + 4);
            float f[8] = {x0.x, x0.y, x0.z, x0.w, x1.x, x1.y, x1.z, x1.w};
            uint32_t p[4];
#pragma unroll
            for (int z = 0; z < 4; ++z) {
                float a = f[2 * z],     sa = a / (1.0f + __expf(-a));
                float b = f[2 * z + 1], sb = b / (1.0f + __expf(-b));
                p[z] = pack2(sa, sb);
            }
            sts16(dst + (qb + half) * 16, p[0], p[1], p[2], p[3]);
        }
    }
}

// -------------------------------------------------------------- main -------
__global__ __launch_bounds__(384, 2)
void kan_mma_kernel(const float* __restrict__ input,   // [16,64,64,32]
                    const float* __restrict__ bias,    // [128]
                    float* __restrict__ out) {         // [61504,128]
    extern __shared__ char smem[];
    const uint32_t sb = (uint32_t)__cvta_generic_to_shared(smem);
    const uint32_t Ab = sb;
    const uint32_t Wb = sb + SMEM_W_OFF;

    const int tid = threadIdx.x;
    const int l   = tid & 31;
    const int wid = tid >> 5;

    if (wid < 8) {
        // ==================== CONSUMER: pure MMA stream ====================
        const int wm = wid >> 1;       // 0..3 : M warp row (16 rows)
        const int wn = wid & 1;        // 0..1 : N warp col (64 cols)
        const uint32_t aaddr0 =
            (uint32_t)((wm * 16 + (l & 15)) * ASTB + (l >> 4) * 16);
        const uint32_t wfrag_off = (uint32_t)(l * 8);
        const int ob = wn * 64 + (l & 3) * 2;

        float acc[8][4];
#pragma unroll
        for (int nf = 0; nf < 8; ++nf) {
            float b0 = bias[ob + nf * 8];
            float b1 = bias[ob + nf * 8 + 1];
            acc[nf][0] = b0; acc[nf][1] = b1;
            acc[nf][2] = b0; acc[nf][3] = b1;
        }

        __syncthreads();               // matches producer prologue barrier

        for (int kt = 0; kt < NKT; ++kt) {
            const uint32_t As = Ab + (kt & 1) * A_STAGE_B;
            const uint32_t Ws = Wb + (kt % 3) * W_STAGE_B;
#pragma unroll
            for (int ks = 0; ks < 2; ++ks) {
                uint32_t a[4];
                ldsm4(As + aaddr0 + ks * 32, a);
#pragma unroll
                for (int nf = 0; nf < 8; ++nf) {
                    uint32_t b0, b1;
                    lds_v2(Ws + ks * 4096 + (wn * 8 + nf) * 256 + wfrag_off,
                           b0, b1);
                    mma16(acc[nf], a, b0, b1);
                }
            }
            __syncthreads();
        }

        // ---- epilogue: direct float2 stores (bias folded; exact fit) ----
        const int r0 = blockIdx.x * BM + wm * 16 + (l >> 2);
#pragma unroll
        for (int nf = 0; nf < 8; ++nf) {
            int o = ob + nf * 8;
            *reinterpret_cast<float2*>(out + (size_t)r0 * FILTERS + o) =
                make_float2(acc[nf][0], acc[nf][1]);
            *reinterpret_cast<float2*>(out + (size_t)(r0 + 8) * FILTERS + o) =
                make_float2(acc[nf][2], acc[nf][3]);
        }
    } else {
        // ==================== PRODUCER: A build + W staging ================
        const int ptid = tid - 256;    // 0..127
        const int brow = ptid & 63;
        const int qb   = (ptid >> 6) * 2;          // quarter-pair base {0,2}
        const uint32_t arow = Ab + (uint32_t)brow * ASTB;

        int n  = blockIdx.x * BM + brow;           // exact fit
        int bb = n / 3844;                         // 62*62
        int rr = n - bb * 3844;
        int yy = rr / 62;
        int xx = rr - yy * 62;
        const float* rowbase = input + ((bb * 64 + yy) * 64 + xx) * 32;

        // prologue: W groups for tiles 0,1 ; build A tile 0 ; prefetch x(1)
        {
            const char* wsrc = (const char*)g_Wh;
#pragma unroll
            for (int v = 0; v < 4; ++v)
                cpasync16(Wb + v * 2048 + ptid * 16, wsrc + v * 2048 + ptid * 16);
            CP_COMMIT();                            // group: tile 0
#pragma unroll
            for (int v = 0; v < 4; ++v)
                cpasync16(Wb + W_STAGE_B + v * 2048 + ptid * 16,
                          wsrc + W_STAGE_B + v * 2048 + ptid * 16);
            CP_COMMIT();                            // group: tile 1
            float2 x0 = prefetch_x2(0, qb, rowbase);
            build_pair(0, qb, x0, arow, rowbase);
            CP_WAIT1();                             // tile 0 W ready
        }
        float2 xcur = prefetch_x2(1, qb, rowbase);  // for build of tile 1
        __syncthreads();

        for (int kt = 0; kt < NKT; ++kt) {
            // issue W cp.async for tile kt+2 (always commit for accounting)
            if (kt + 2 < NKT) {
                const char* wsrc = (const char*)g_Wh + (size_t)(kt + 2) * W_STAGE_B;
                const uint32_t wdst = Wb + ((kt + 2) % 3) * W_STAGE_B;
#pragma unroll
                for (int v = 0; v < 4; ++v)
                    cpasync16(wdst + v * 2048 + ptid * 16,
                              wsrc + v * 2048 + ptid * 16);
            }
            CP_COMMIT();

            // input prefetch for build of tile kt+2 (full interval to land)
            float2 xfut = make_float2(0.f, 0.f);
            if (kt + 2 < NSPLINE)
                xfut = prefetch_x2(kt + 2, qb, rowbase);

            // build A for tile kt+1 (value prefetched last interval)
            if (kt + 1 < NKT)
                build_pair(kt + 1, qb, xcur,
                           arow + ((kt + 1) & 1) * A_STAGE_B, rowbase);
            xcur = xfut;

            CP_WAIT1();        // W for tile kt+1 complete; kt+2 in flight
            __syncthreads();
        }
        // no epilogue work for producers
    }
}

// ------------------------------------------------------------- launcher ----
extern "C" void kernel_launch(void* const* d_in, const int* in_sizes, int n_in,
                              void* d_out, int out_size) {
    const float* input = (const float*)d_in[0];   // (16,64,64,32)
    const float* sk    = (const float*)d_in[1];   // (288,8,128)
    const float* sc    = (const float*)d_in[2];   // (288,128)
    const float* bias  = (const float*)d_in[3];   // (128,)
    float* out = (float*)d_out;
    (void)in_sizes; (void)n_in; (void)out_size;

    static bool attr_done = false;
    if (!attr_done) {
        cudaFuncSetAttribute(kan_mma_kernel,
                             cudaFuncAttributeMaxDynamicSharedMemorySize, SMEM_TOTAL);
        attr_done = true;
    }

    int wwords = K_TOTAL * FILTERS / 2;
    fuse_weights<<<(wwords + 255) / 256, 256>>>(sk, sc);

    int blocks = N_TOTAL / BM;          // 961, exact
    kan_mma_kernel<<<blocks, 384, SMEM_TOTAL>>>(input, bias, out);
}

// round 13
// speedup vs baseline: 2.1577x; 2.1577x over previous
#include <cuda_runtime.h>
#include <cuda_fp16.h>
#include <math.h>
#include <stdint.h>

// ============================================================================
// ConvolutionKAN as mma.sync fp16 GEMM (sm_100-safe, fp32 accumulate):
//   out[61504,128] = A[61504,2592] @ W[2592,128] + bias
//   K layout: k in [0,2304): spline (i=k>>3, c=k&7, uniform cubic B-spline
//             closed form); k in [2304,2592): silu(x_i).
// R13: 128-thread CTAs (4 warps), warp tile 32x64, 5 CTAs/SM -> 5 small
//      independent barrier domains; B smem traffic halved; spline eval via
//      zero-store + dynamic-offset half scatter (no select chains).
// ============================================================================

#define N_TOTAL   61504
#define K_TOTAL   2592
#define FILTERS   128
#define BM        64
#define NKT       81                   // 2592 / 32
#define NSPLINE   72                   // tiles 0..71: spline, 72..80: silu

#define ASTB       80                  // A row stride (bytes), conflict-free
#define A_STAGE_B  (BM * ASTB)         // 5120
#define W_STAGE_B  8192                // 32k * 128o * 2B (frag-ordered)
#define SMEM_W_OFF (2 * A_STAGE_B)     // 10240
#define SMEM_TOTAL (2 * A_STAGE_B + 3 * W_STAGE_B)   // 34816 B

// W in m16n8k16 B-fragment word order per 32-k tile (2048 words):
//   word = ks*1024 + ob*64 + lane*2 + r
//   halfs: k = kt*32 + ks*16 + 2*(lane&3) + 8*r + hh,  o = ob*8 + (lane>>2)
__device__ __half g_Wh[K_TOTAL * FILTERS];

// ---------------------------------------------------------------- helpers --
__device__ __forceinline__ uint32_t pack2(float a, float b) {
    __half2 h = __floats2half2_rn(a, b);
    return *reinterpret_cast<uint32_t*>(&h);
}
__device__ __forceinline__ void sts16(uint32_t addr, uint32_t a, uint32_t b,
                                      uint32_t c, uint32_t d) {
    asm volatile("st.shared.v4.b32 [%0], {%1,%2,%3,%4};"
                 :: "r"(addr), "r"(a), "r"(b), "r"(c), "r"(d) : "memory");
}
__device__ __forceinline__ void sts_h(uint32_t addr, unsigned short v) {
    asm volatile("st.shared.b16 [%0], %1;" :: "r"(addr), "h"(v) : "memory");
}
__device__ __forceinline__ void lds_v2(uint32_t addr, uint32_t& a, uint32_t& b) {
    asm volatile("ld.shared.v2.b32 {%0,%1}, [%2];" : "=r"(a), "=r"(b) : "r"(addr));
}
__device__ __forceinline__ void ldsm4(uint32_t addr, uint32_t* r) {
    asm volatile("ldmatrix.sync.aligned.m8n8.x4.shared.b16 {%0,%1,%2,%3}, [%4];"
                 : "=r"(r[0]), "=r"(r[1]), "=r"(r[2]), "=r"(r[3]) : "r"(addr));
}
__device__ __forceinline__ void mma16(float* d, const uint32_t* a,
                                      uint32_t b0, uint32_t b1) {
    asm volatile(
        "mma.sync.aligned.m16n8k16.row.col.f32.f16.f16.f32 "
        "{%0,%1,%2,%3}, {%4,%5,%6,%7}, {%8,%9}, {%0,%1,%2,%3};"
        : "+f"(d[0]), "+f"(d[1]), "+f"(d[2]), "+f"(d[3])
        : "r"(a[0]), "r"(a[1]), "r"(a[2]), "r"(a[3]), "r"(b0), "r"(b1));
}
__device__ __forceinline__ void cpasync16(uint32_t saddr, const void* gptr) {
    asm volatile("cp.async.cg.shared.global [%0], [%1], 16;"
                 :: "r"(saddr), "l"(__cvta_generic_to_global(gptr)) : "memory");
}
#define CP_COMMIT()  asm volatile("cp.async.commit_group;" ::: "memory")
#define CP_WAIT1()   asm volatile("cp.async.wait_group 1;" ::: "memory")

// --------------------------------------------------------- weight fuse -----
__global__ void fuse_weights(const float* __restrict__ sk,   // [288,8,128]
                             const float* __restrict__ sc) { // [288,128]
    int w = blockIdx.x * 256 + threadIdx.x;                  // uint32 words
    if (w >= K_TOTAL * FILTERS / 2) return;
    int kt   = w >> 11;                 // 2048 words per 32-k tile
    int rem  = w & 2047;
    int ks   = rem >> 10;
    int ob   = (rem >> 6) & 15;
    int l    = (rem >> 1) & 31;
    int r    = rem & 1;
    int o    = ob * 8 + (l >> 2);
    int kb   = kt * 32 + ks * 16 + 2 * (l & 3) + 8 * r;
    float v[2];
#pragma unroll
    for (int hh = 0; hh < 2; ++hh) {
        int k = kb + hh;
        if (k < 2304) {
            int i = k >> 3;
            v[hh] = sk[k * 128 + o] * sc[i * 128 + o];
        } else {
            v[hh] = sc[(k - 2304) * 128 + o];
        }
    }
    ((uint32_t*)g_Wh)[w] = pack2(v[0], v[1]);
}

// ------------------------------------------------------------ A builder ----
// Thread (row = tid>>1, h = tid&1) builds quarters 2h,2h+1 of its row (32 B).
//   spline tile kt: channels i = kt*4 + 2h, +1
//   silu tile:      channels 16h .. 16h+15 of the 32-block
__device__ __forceinline__ float2 prefetch_x2(int kt, int h,
                                              const float* __restrict__ rowbase) {
    int i  = kt * 4 + 2 * h;
    int di = i / 96;
    int rm = i - di * 96;
    return *reinterpret_cast<const float2*>(
        rowbase + (di * 64 + (rm >> 5)) * 32 + (rm & 31));
}

// zero the 8-half slot, then scatter the 4 nonzero bases at byte offset 2j
__device__ __forceinline__ void spline_scatter(float x, uint32_t dst) {
    float tp = (x + 1.0f) * 2.5f;                    // uniform grid, h = 0.4
    int j = (int)floorf(tp);
    j = max(0, min(4, j));
    float u  = tp - (float)j;
    float um = 1.0f - u;
    float u2 = u * u, u3 = u2 * u;
    float b0 = um * um * um * (1.0f / 6.0f);
    float b1 = (3.0f * u3 - 6.0f * u2 + 4.0f) * (1.0f / 6.0f);
    float b2 = (-3.0f * u3 + 3.0f * u2 + 3.0f * u + 1.0f) * (1.0f / 6.0f);
    float b3 = u3 * (1.0f / 6.0f);
    sts16(dst, 0u, 0u, 0u, 0u);
    uint32_t da = dst + 2 * j;
    sts_h(da,     __half_as_ushort(__float2half_rn(b0)));
    sts_h(da + 2, __half_as_ushort(__float2half_rn(b1)));
    sts_h(da + 4, __half_as_ushort(__float2half_rn(b2)));
    sts_h(da + 6, __half_as_ushort(__float2half_rn(b3)));
}

__device__ __forceinline__ void build_half(int kt, int h, float2 xv,
                                           uint32_t rowdst,
                                           const float* __restrict__ rowbase) {
    if (kt < NSPLINE) {
        spline_scatter(xv.x, rowdst + h * 32);
        spline_scatter(xv.y, rowdst + h * 32 + 16);
    } else {
        int ib = kt - NSPLINE;                       // 32-channel block
        int di = ib / 3;
        int dj = ib - di * 3;
        const float* src = rowbase + (di * 64 + dj) * 32 + h * 16;
#pragma unroll
        for (int q = 0; q < 2; ++q) {
            float4 x0 = *reinterpret_cast<const float4*>(src + q * 8);
            float4 x1 = *reinterpret_cast<const float4*>(src + q * 8 + 4);
            float f[8] = {x0.x, x0.y, x0.z, x0.w, x1.x, x1.y, x1.z, x1.w};
            uint32_t p[4];
#pragma unroll
            for (int z = 0; z < 4; ++z) {
                float a = f[2 * z],     sa = a / (1.0f + __expf(-a));
                float b = f[2 * z + 1], sb = b / (1.0f + __expf(-b));
                p[z] = pack2(sa, sb);
            }
            sts16(rowdst + h * 32 + q * 16, p[0], p[1], p[2], p[3]);
        }
    }
}

// -------------------------------------------------------------- main -------
__global__ __launch_bounds__(128, 5)
void kan_mma_kernel(const float* __restrict__ input,   // [16,64,64,32]
                    const float* __restrict__ bias,    // [128]
                    float* __restrict__ out) {         // [61504,128]
    extern __shared__ char smem[];
    const uint32_t sb = (uint32_t)__cvta_generic_to_shared(smem);
    const uint32_t Ab = sb;
    const uint32_t Wb = sb + SMEM_W_OFF;

    const int tid = threadIdx.x;
    const int l   = tid & 31;
    const int wid = tid >> 5;
    const int wm  = wid >> 1;          // 0..1 : M warp row (32 rows)
    const int wn  = wid & 1;           // 0..1 : N warp col (64 cols)

    // builder role: row = tid>>1, half h = tid&1
    const int brow = tid >> 1;
    const int bh   = tid & 1;
    const uint32_t arow = Ab + (uint32_t)brow * ASTB;

    int n  = blockIdx.x * BM + brow;    // exact fit: 961 * 64 = 61504
    int bb = n / 3844;                  // 62*62
    int rr = n - bb * 3844;
    int yy = rr / 62;
    int xx = rr - yy * 62;
    const float* rowbase = input + ((bb * 64 + yy) * 64 + xx) * 32;

    // fragment address pieces (fixed per thread)
    const uint32_t aaddr0    = (uint32_t)((wm * 32 + (l & 15)) * ASTB + (l >> 4) * 16);
    const uint32_t wfrag_off = (uint32_t)(l * 8);
    const int      ob        = wn * 64 + (l & 3) * 2;

    // accumulators initialized with bias (warp tile 32 x 64: 2 mf x 8 nf)
    float acc[2][8][4];
#pragma unroll
    for (int nf = 0; nf < 8; ++nf) {
        float b0 = bias[ob + nf * 8];
        float b1 = bias[ob + nf * 8 + 1];
#pragma unroll
        for (int mf = 0; mf < 2; ++mf) {
            acc[mf][nf][0] = b0; acc[mf][nf][1] = b1;
            acc[mf][nf][2] = b0; acc[mf][nf][3] = b1;
        }
    }

    // ---- prologue: W groups for tiles 0,1 ; build A tile 0 ; prefetch x(1) --
    {
        const char* wsrc = (const char*)g_Wh;
#pragma unroll
        for (int v = 0; v < 4; ++v)
            cpasync16(Wb + v * 2048 + tid * 16, wsrc + v * 2048 + tid * 16);
        CP_COMMIT();                                   // group: tile 0
#pragma unroll
        for (int v = 0; v < 4; ++v)
            cpasync16(Wb + W_STAGE_B + v * 2048 + tid * 16,
                      wsrc + W_STAGE_B + v * 2048 + tid * 16);
        CP_COMMIT();                                   // group: tile 1
        float2 x0 = prefetch_x2(0, bh, rowbase);
        build_half(0, bh, x0, arow, rowbase);
        CP_WAIT1();                                    // tile 0 W ready
    }
    float2 xcur = prefetch_x2(1, bh, rowbase);         // for build of tile 1
    __syncthreads();

    for (int kt = 0; kt < NKT; ++kt) {
        // ---- issue W cp.async for tile kt+2 (always commit) ----
        if (kt + 2 < NKT) {
            const char* wsrc = (const char*)g_Wh + (size_t)(kt + 2) * W_STAGE_B;
            const uint32_t wdst = Wb + ((kt + 2) % 3) * W_STAGE_B;
#pragma unroll
            for (int v = 0; v < 4; ++v)
                cpasync16(wdst + v * 2048 + tid * 16, wsrc + v * 2048 + tid * 16);
        }
        CP_COMMIT();

        // input prefetch for build of tile kt+2
        float2 xfut = make_float2(0.f, 0.f);
        if (kt + 2 < NSPLINE)
            xfut = prefetch_x2(kt + 2, bh, rowbase);

        // ---- compute tile kt: warp 32(M) x 64(N), k=32 (2 x k16) ----
        const uint32_t As = Ab + (kt & 1) * A_STAGE_B;
        const uint32_t Ws = Wb + (kt % 3) * W_STAGE_B;
#pragma unroll
        for (int ks = 0; ks < 2; ++ks) {
            uint32_t a[2][4];
#pragma unroll
            for (int mf = 0; mf < 2; ++mf)
                ldsm4(As + aaddr0 + mf * (16 * ASTB) + ks * 32, a[mf]);
#pragma unroll
            for (int nf = 0; nf < 8; ++nf) {
                uint32_t b0, b1;
                lds_v2(Ws + ks * 4096 + (wn * 8 + nf) * 256 + wfrag_off, b0, b1);
#pragma unroll
                for (int mf = 0; mf < 2; ++mf)
                    mma16(acc[mf][nf], a[mf], b0, b1);
            }
        }

        // ---- builder math + STS for tile kt+1 ----
        if (kt + 1 < NKT)
            build_half(kt + 1, bh, xcur, arow + ((kt + 1) & 1) * A_STAGE_B,
                       rowbase);
        xcur = xfut;

        CP_WAIT1();        // W for tile kt+1 complete; kt+2 stays in flight
        __syncthreads();
    }

    // ---- epilogue: direct float2 stores (bias folded; exact fit) ----
#pragma unroll
    for (int mf = 0; mf < 2; ++mf) {
        const int r0 = blockIdx.x * BM + wm * 32 + mf * 16 + (l >> 2);
#pragma unroll
        for (int nf = 0; nf < 8; ++nf) {
            int o = ob + nf * 8;
            *reinterpret_cast<float2*>(out + (size_t)r0 * FILTERS + o) =
                make_float2(acc[mf][nf][0], acc[mf][nf][1]);
            *reinterpret_cast<float2*>(out + (size_t)(r0 + 8) * FILTERS + o) =
                make_float2(acc[mf][nf][2], acc[mf][nf][3]);
        }
    }
}

// ------------------------------------------------------------- launcher ----
extern "C" void kernel_launch(void* const* d_in, const int* in_sizes, int n_in,
                              void* d_out, int out_size) {
    const float* input = (const float*)d_in[0];   // (16,64,64,32)
    const float* sk    = (const float*)d_in[1];   // (288,8,128)
    const float* sc    = (const float*)d_in[2];   // (288,128)
    const float* bias  = (const float*)d_in[3];   // (128,)
    float* out = (float*)d_out;
    (void)in_sizes; (void)n_in; (void)out_size;

    static bool attr_done = false;
    if (!attr_done) {
        cudaFuncSetAttribute(kan_mma_kernel,
                             cudaFuncAttributeMaxDynamicSharedMemorySize, SMEM_TOTAL);
        attr_done = true;
    }

    int wwords = K_TOTAL * FILTERS / 2;
    fuse_weights<<<(wwords + 255) / 256, 256>>>(sk, sc);

    int blocks = N_TOTAL / BM;          // 961, exact
    kan_mma_kernel<<<blocks, 128, SMEM_TOTAL>>>(input, bias, out);
}

// round 14
// speedup vs baseline: 2.1732x; 1.0072x over previous
#include <cuda_runtime.h>
#include <cuda_fp16.h>
#include <math.h>
#include <stdint.h>

// ============================================================================
// ConvolutionKAN as mma.sync fp16 GEMM (sm_100-safe, fp32 accumulate):
//   out[61504,128] = A[61504,2592] @ W[2592,128] + bias
//   K layout: k in [0,2304): spline (i=k>>3, c=k&7, uniform cubic B-spline
//             closed form); k in [2304,2592): silu(x_i).
// R14: R13 + DYNAMIC tile scheduler. 740 persistent CTAs pop M-tiles from a
//      global atomic counter -> no 30%-full second wave, no static stragglers.
// ============================================================================

#define N_TOTAL   61504
#define K_TOTAL   2592
#define FILTERS   128
#define BM        64
#define NMT       961                  // M tiles (exact: 961*64 = 61504)
#define NKT       81                   // 2592 / 32
#define NSPLINE   72                   // tiles 0..71: spline, 72..80: silu
#define GRID_P    740                  // 5 CTAs/SM * 148 SMs

#define ASTB       80                  // A row stride (bytes), conflict-free
#define A_STAGE_B  (BM * ASTB)         // 5120
#define W_STAGE_B  8192                // 32k * 128o * 2B (frag-ordered)
#define SMEM_W_OFF (2 * A_STAGE_B)     // 10240
#define SMEM_SCHED (2 * A_STAGE_B + 3 * W_STAGE_B)   // 34816
#define SMEM_TOTAL (SMEM_SCHED + 16)                 // + scheduler slot

// W in m16n8k16 B-fragment word order per 32-k tile (2048 words):
//   word = ks*1024 + ob*64 + lane*2 + r
//   halfs: k = kt*32 + ks*16 + 2*(lane&3) + 8*r + hh,  o = ob*8 + (lane>>2)
__device__ __half g_Wh[K_TOTAL * FILTERS];
__device__ unsigned int g_tile_ctr;

// ---------------------------------------------------------------- helpers --
__device__ __forceinline__ uint32_t pack2(float a, float b) {
    __half2 h = __floats2half2_rn(a, b);
    return *reinterpret_cast<uint32_t*>(&h);
}
__device__ __forceinline__ void sts16(uint32_t addr, uint32_t a, uint32_t b,
                                      uint32_t c, uint32_t d) {
    asm volatile("st.shared.v4.b32 [%0], {%1,%2,%3,%4};"
                 :: "r"(addr), "r"(a), "r"(b), "r"(c), "r"(d) : "memory");
}
__device__ __forceinline__ void sts_h(uint32_t addr, unsigned short v) {
    asm volatile("st.shared.b16 [%0], %1;" :: "r"(addr), "h"(v) : "memory");
}
__device__ __forceinline__ void lds_v2(uint32_t addr, uint32_t& a, uint32_t& b) {
    asm volatile("ld.shared.v2.b32 {%0,%1}, [%2];" : "=r"(a), "=r"(b) : "r"(addr));
}
__device__ __forceinline__ void ldsm4(uint32_t addr, uint32_t* r) {
    asm volatile("ldmatrix.sync.aligned.m8n8.x4.shared.b16 {%0,%1,%2,%3}, [%4];"
                 : "=r"(r[0]), "=r"(r[1]), "=r"(r[2]), "=r"(r[3]) : "r"(addr));
}
__device__ __forceinline__ void mma16(float* d, const uint32_t* a,
                                      uint32_t b0, uint32_t b1) {
    asm volatile(
        "mma.sync.aligned.m16n8k16.row.col.f32.f16.f16.f32 "
        "{%0,%1,%2,%3}, {%4,%5,%6,%7}, {%8,%9}, {%0,%1,%2,%3};"
        : "+f"(d[0]), "+f"(d[1]), "+f"(d[2]), "+f"(d[3])
        : "r"(a[0]), "r"(a[1]), "r"(a[2]), "r"(a[3]), "r"(b0), "r"(b1));
}
__device__ __forceinline__ void cpasync16(uint32_t saddr, const void* gptr) {
    asm volatile("cp.async.cg.shared.global [%0], [%1], 16;"
                 :: "r"(saddr), "l"(__cvta_generic_to_global(gptr)) : "memory");
}
#define CP_COMMIT()  asm volatile("cp.async.commit_group;" ::: "memory")
#define CP_WAIT1()   asm volatile("cp.async.wait_group 1;" ::: "memory")

// --------------------------------------------------------- weight fuse -----
__global__ void fuse_weights(const float* __restrict__ sk,   // [288,8,128]
                             const float* __restrict__ sc) { // [288,128]
    if (blockIdx.x == 0 && threadIdx.x == 0) g_tile_ctr = 0;  // scheduler reset
    int w = blockIdx.x * 256 + threadIdx.x;                  // uint32 words
    if (w >= K_TOTAL * FILTERS / 2) return;
    int kt   = w >> 11;                 // 2048 words per 32-k tile
    int rem  = w & 2047;
    int ks   = rem >> 10;
    int ob   = (rem >> 6) & 15;
    int l    = (rem >> 1) & 31;
    int r    = rem & 1;
    int o    = ob * 8 + (l >> 2);
    int kb   = kt * 32 + ks * 16 + 2 * (l & 3) + 8 * r;
    float v[2];
#pragma unroll
    for (int hh = 0; hh < 2; ++hh) {
        int k = kb + hh;
        if (k < 2304) {
            int i = k >> 3;
            v[hh] = sk[k * 128 + o] * sc[i * 128 + o];
        } else {
            v[hh] = sc[(k - 2304) * 128 + o];
        }
    }
    ((uint32_t*)g_Wh)[w] = pack2(v[0], v[1]);
}

// ------------------------------------------------------------ A builder ----
__device__ __forceinline__ float2 prefetch_x2(int kt, int h,
                                              const float* __restrict__ rowbase) {
    int i  = kt * 4 + 2 * h;
    int di = i / 96;
    int rm = i - di * 96;
    return *reinterpret_cast<const float2*>(
        rowbase + (di * 64 + (rm >> 5)) * 32 + (rm & 31));
}

// zero the 8-half slot, then scatter the 4 nonzero bases at byte offset 2j
__device__ __forceinline__ void spline_scatter(float x, uint32_t dst) {
    float tp = (x + 1.0f) * 2.5f;                    // uniform grid, h = 0.4
    int j = (int)floorf(tp);
    j = max(0, min(4, j));
    float u  = tp - (float)j;
    float um = 1.0f - u;
    float u2 = u * u, u3 = u2 * u;
    float b0 = um * um * um * (1.0f / 6.0f);
    float b1 = (3.0f * u3 - 6.0f * u2 + 4.0f) * (1.0f / 6.0f);
    float b2 = (-3.0f * u3 + 3.0f * u2 + 3.0f * u + 1.0f) * (1.0f / 6.0f);
    float b3 = u3 * (1.0f / 6.0f);
    sts16(dst, 0u, 0u, 0u, 0u);
    uint32_t da = dst + 2 * j;
    sts_h(da,     __half_as_ushort(__float2half_rn(b0)));
    sts_h(da + 2, __half_as_ushort(__float2half_rn(b1)));
    sts_h(da + 4, __half_as_ushort(__float2half_rn(b2)));
    sts_h(da + 6, __half_as_ushort(__float2half_rn(b3)));
}

__device__ __forceinline__ void build_half(int kt, int h, float2 xv,
                                           uint32_t rowdst,
                                           const float* __restrict__ rowbase) {
    if (kt < NSPLINE) {
        spline_scatter(xv.x, rowdst + h * 32);
        spline_scatter(xv.y, rowdst + h * 32 + 16);
    } else {
        int ib = kt - NSPLINE;                       // 32-channel block
        int di = ib / 3;
        int dj = ib - di * 3;
        const float* src = rowbase + (di * 64 + dj) * 32 + h * 16;
#pragma unroll
        for (int q = 0; q < 2; ++q) {
            float4 x0 = *reinterpret_cast<const float4*>(src + q * 8);
            float4 x1 = *reinterpret_cast<const float4*>(src + q * 8 + 4);
            float f[8] = {x0.x, x0.y, x0.z, x0.w, x1.x, x1.y, x1.z, x1.w};
            uint32_t p[4];
#pragma unroll
            for (int z = 0; z < 4; ++z) {
                float a = f[2 * z],     sa = a / (1.0f + __expf(-a));
                float b = f[2 * z + 1], sb = b / (1.0f + __expf(-b));
                p[z] = pack2(sa, sb);
            }
            sts16(rowdst + h * 32 + q * 16, p[0], p[1], p[2], p[3]);
        }
    }
}

// -------------------------------------------------------------- main -------
__global__ __launch_bounds__(128, 5)
void kan_mma_kernel(const float* __restrict__ input,   // [16,64,64,32]
                    const float* __restrict__ bias,    // [128]
                    float* __restrict__ out) {         // [61504,128]
    extern __shared__ char smem[];
    const uint32_t sb = (uint32_t)__cvta_generic_to_shared(smem);
    const uint32_t Ab = sb;
    const uint32_t Wb = sb + SMEM_W_OFF;
    volatile unsigned int* mt_slot =
        reinterpret_cast<volatile unsigned int*>(smem + SMEM_SCHED);

    const int tid = threadIdx.x;
    const int l   = tid & 31;
    const int wid = tid >> 5;
    const int wm  = wid >> 1;          // 0..1 : M warp row (32 rows)
    const int wn  = wid & 1;           // 0..1 : N warp col (64 cols)

    // builder role: row = tid>>1, half h = tid&1
    const int brow = tid >> 1;
    const int bh   = tid & 1;
    const uint32_t arow = Ab + (uint32_t)brow * ASTB;

    // fragment address pieces (fixed per thread)
    const uint32_t aaddr0    = (uint32_t)((wm * 32 + (l & 15)) * ASTB + (l >> 4) * 16);
    const uint32_t wfrag_off = (uint32_t)(l * 8);
    const int      ob        = wn * 64 + (l & 3) * 2;

    // cache bias once (constant across tiles)
    float bias0[8], bias1[8];
#pragma unroll
    for (int nf = 0; nf < 8; ++nf) {
        bias0[nf] = bias[ob + nf * 8];
        bias1[nf] = bias[ob + nf * 8 + 1];
    }

    // ==================== dynamic tile loop ====================
    for (;;) {
        if (tid == 0) *mt_slot = atomicAdd(&g_tile_ctr, 1u);
        __syncthreads();
        const int mt = (int)*mt_slot;
        __syncthreads();               // mt consumed before next overwrite
        if (mt >= NMT) break;

        int n  = mt * BM + brow;       // exact fit
        int bb = n / 3844;             // 62*62
        int rr = n - bb * 3844;
        int yy = rr / 62;
        int xx = rr - yy * 62;
        const float* rowbase = input + ((bb * 64 + yy) * 64 + xx) * 32;

        // accumulators initialized with bias
        float acc[2][8][4];
#pragma unroll
        for (int nf = 0; nf < 8; ++nf) {
#pragma unroll
            for (int mf = 0; mf < 2; ++mf) {
                acc[mf][nf][0] = bias0[nf]; acc[mf][nf][1] = bias1[nf];
                acc[mf][nf][2] = bias0[nf]; acc[mf][nf][3] = bias1[nf];
            }
        }

        // ---- prologue: W groups for tiles 0,1 ; build A tile 0 ----
        {
            const char* wsrc = (const char*)g_Wh;
#pragma unroll
            for (int v = 0; v < 4; ++v)
                cpasync16(Wb + v * 2048 + tid * 16, wsrc + v * 2048 + tid * 16);
            CP_COMMIT();                               // group: tile 0
#pragma unroll
            for (int v = 0; v < 4; ++v)
                cpasync16(Wb + W_STAGE_B + v * 2048 + tid * 16,
                          wsrc + W_STAGE_B + v * 2048 + tid * 16);
            CP_COMMIT();                               // group: tile 1
            float2 x0 = prefetch_x2(0, bh, rowbase);
            build_half(0, bh, x0, arow, rowbase);
            CP_WAIT1();                                // tile 0 W ready
        }
        float2 xcur = prefetch_x2(1, bh, rowbase);     // for build of tile 1
        __syncthreads();

        for (int kt = 0; kt < NKT; ++kt) {
            // ---- issue W cp.async for tile kt+2 (always commit) ----
            if (kt + 2 < NKT) {
                const char* wsrc = (const char*)g_Wh + (size_t)(kt + 2) * W_STAGE_B;
                const uint32_t wdst = Wb + ((kt + 2) % 3) * W_STAGE_B;
#pragma unroll
                for (int v = 0; v < 4; ++v)
                    cpasync16(wdst + v * 2048 + tid * 16,
                              wsrc + v * 2048 + tid * 16);
            }
            CP_COMMIT();

            // input prefetch for build of tile kt+2
            float2 xfut = make_float2(0.f, 0.f);
            if (kt + 2 < NSPLINE)
                xfut = prefetch_x2(kt + 2, bh, rowbase);

            // ---- compute tile kt: warp 32(M) x 64(N), k=32 (2 x k16) ----
            const uint32_t As = Ab + (kt & 1) * A_STAGE_B;
            const uint32_t Ws = Wb + (kt % 3) * W_STAGE_B;
#pragma unroll
            for (int ks = 0; ks < 2; ++ks) {
                uint32_t a[2][4];
#pragma unroll
                for (int mf = 0; mf < 2; ++mf)
                    ldsm4(As + aaddr0 + mf * (16 * ASTB) + ks * 32, a[mf]);
#pragma unroll
                for (int nf = 0; nf < 8; ++nf) {
                    uint32_t b0, b1;
                    lds_v2(Ws + ks * 4096 + (wn * 8 + nf) * 256 + wfrag_off,
                           b0, b1);
#pragma unroll
                    for (int mf = 0; mf < 2; ++mf)
                        mma16(acc[mf][nf], a[mf], b0, b1);
                }
            }

            // ---- builder math + STS for tile kt+1 ----
            if (kt + 1 < NKT)
                build_half(kt + 1, bh, xcur, arow + ((kt + 1) & 1) * A_STAGE_B,
                           rowbase);
            xcur = xfut;

            CP_WAIT1();    // W for tile kt+1 complete; kt+2 stays in flight
            __syncthreads();
        }

        // ---- epilogue: direct float2 stores (bias folded; exact fit) ----
#pragma unroll
        for (int mf = 0; mf < 2; ++mf) {
            const int r0 = mt * BM + wm * 32 + mf * 16 + (l >> 2);
#pragma unroll
            for (int nf = 0; nf < 8; ++nf) {
                int o = ob + nf * 8;
                *reinterpret_cast<float2*>(out + (size_t)r0 * FILTERS + o) =
                    make_float2(acc[mf][nf][0], acc[mf][nf][1]);
                *reinterpret_cast<float2*>(out + (size_t)(r0 + 8) * FILTERS + o) =
                    make_float2(acc[mf][nf][2], acc[mf][nf][3]);
            }
        }
        // k-loop's final __syncthreads already ordered smem reads; epilogue
        // touches only registers + gmem, so looping back to the pop is safe.
    }
}

// ------------------------------------------------------------- launcher ----
extern "C" void kernel_launch(void* const* d_in, const int* in_sizes, int n_in,
                              void* d_out, int out_size) {
    const float* input = (const float*)d_in[0];   // (16,64,64,32)
    const float* sk    = (const float*)d_in[1];   // (288,8,128)
    const float* sc    = (const float*)d_in[2];   // (288,128)
    const float* bias  = (const float*)d_in[3];   // (128,)
    float* out = (float*)d_out;
    (void)in_sizes; (void)n_in; (void)out_size;

    static bool attr_done = false;
    if (!attr_done) {
        cudaFuncSetAttribute(kan_mma_kernel,
                             cudaFuncAttributeMaxDynamicSharedMemorySize, SMEM_TOTAL);
        attr_done = true;
    }

    int wwords = K_TOTAL * FILTERS / 2;
    fuse_weights<<<(wwords + 255) / 256, 256>>>(sk, sc);   // also resets g_tile_ctr

    kan_mma_kernel<<<GRID_P, 128, SMEM_TOTAL>>>(input, bias, out);
}